// round 3
// baseline (speedup 1.0000x reference)
#include <cuda_runtime.h>
#include <math.h>

#define NN    256
#define FEATD 1024
#define HIDR  256
#define HEADS 4
#define GCH   256
#define H1DIM 1024   // HEADS*GCH
#define OUTD  21
#define TOPK  3
#define E_TOT (NN*TOPK + NN)   // 1024 edges

// ---------------- scratch (device globals; no allocation allowed) ----------
__device__ __align__(16) float g_A[NN*HIDR];
__device__ __align__(16) float g_B[NN*HIDR];
__device__ __align__(16) float g_rel[NN*NN];
__device__ int   g_top[NN*TOPK];
__device__ int   g_off[NN+1];
__device__ int   g_inc[E_TOT];
__device__ __align__(16) float g_h1[NN*H1DIM];
__device__ float g_ss1[NN*HEADS], g_ds1[NN*HEADS];
__device__ __align__(16) float g_x1[NN*H1DIM];
__device__ __align__(16) float g_h2[NN*OUTD];
__device__ float g_ss2[NN], g_ds2[NN];
__device__ __align__(16) float g_W2T[OUTD*H1DIM];   // W2 transposed [o][c]

// edge id -> source node (edges 0..767 are topk from row e/3; 768.. are loops)
__device__ __forceinline__ int edge_src(int e) {
    return (e < NN * TOPK) ? (e / TOPK) : (e - NN * TOPK);
}

// read a scalar that may have been serialized as int32 or float32
__device__ __forceinline__ float read_dim(const void* p) {
    int iv = *(const int*)p;
    if (iv > 0 && iv < 100000) return (float)iv;
    return *(const float*)p;
}

// ---------------- K1: A = F @ W_fc1[0:1024], B = F @ W_fc1[1024:2048] ------
__global__ void k_ab(const float* __restrict__ feat, const float* __restrict__ Wfc1) {
    __shared__ float  sA[16][33];
    __shared__ float4 sW[16][16];
    int t = threadIdx.x;
    int tx = t & 15, ty = t >> 4;
    int row0 = blockIdx.y * 32;
    int colg = blockIdx.x * 64;
    const float* W;
    float* dst;
    int colL;
    if (colg < 256) { W = Wfc1;                       dst = g_A; colL = colg; }
    else            { W = Wfc1 + (size_t)1024 * HIDR; dst = g_B; colL = colg - 256; }
    float acc[2][4] = {};
    for (int k0 = 0; k0 < FEATD; k0 += 16) {
        if (t < 128) {
            int r = t >> 2, kq = t & 3;
            float4 v = *(const float4*)&feat[(size_t)(row0 + r) * FEATD + k0 + kq * 4];
            sA[kq*4+0][r] = v.x; sA[kq*4+1][r] = v.y; sA[kq*4+2][r] = v.z; sA[kq*4+3][r] = v.w;
        }
        {
            int kr = t >> 4, cq = t & 15;
            sW[kr][cq] = *(const float4*)&W[(size_t)(k0 + kr) * HIDR + colL + cq * 4];
        }
        __syncthreads();
#pragma unroll
        for (int kk = 0; kk < 16; kk++) {
            float a0 = sA[kk][ty], a1 = sA[kk][ty + 16];
            float4 w = sW[kk][tx];
            acc[0][0] += a0 * w.x; acc[0][1] += a0 * w.y; acc[0][2] += a0 * w.z; acc[0][3] += a0 * w.w;
            acc[1][0] += a1 * w.x; acc[1][1] += a1 * w.y; acc[1][2] += a1 * w.z; acc[1][3] += a1 * w.w;
        }
        __syncthreads();
    }
#pragma unroll
    for (int u = 0; u < 2; u++) {
        int r = row0 + ty + u * 16;
        *(float4*)&dst[(size_t)r * HIDR + colL + tx * 4] =
            make_float4(acc[u][0], acc[u][1], acc[u][2], acc[u][3]);
    }
}

// ---------------- K2: rel[i,j] = relu(A[i]+B[j]+bias+geom@Wg) . W_fc2 + b2 -
__global__ void k_rel(const float* __restrict__ boxes,
                      const float* __restrict__ Wfc1,
                      const float* __restrict__ bfc1,
                      const float* __restrict__ Wfc2,
                      const float* __restrict__ bfc2) {
    __shared__ __align__(16) float sAb[8][HIDR];
    __shared__ __align__(16) float sBt[HIDR][68];
    __shared__ __align__(16) float4 sGeo[HIDR];
    __shared__ float sW2[HIDR];
    int t = threadIdx.x;                 // 128
    int il = t >> 4, jg = t & 15, jl = jg * 4;
    int i0 = blockIdx.y * 8, j0 = blockIdx.x * 64;
    const float* Wg = Wfc1 + (size_t)2 * FEATD * HIDR;
    for (int idx = t; idx < 8 * HIDR; idx += 128) {
        int i = idx >> 8, c = idx & 255;
        sAb[i][c] = g_A[(size_t)(i0 + i) * HIDR + c] + bfc1[c];
    }
    for (int idx = t; idx < 64 * HIDR; idx += 128) {
        int j = idx >> 8, c = idx & 255;
        sBt[c][j] = g_B[(size_t)(j0 + j) * HIDR + c];
    }
    for (int c = t; c < HIDR; c += 128) {
        sGeo[c] = make_float4(Wg[c], Wg[HIDR + c], Wg[2 * HIDR + c], Wg[3 * HIDR + c]);
        sW2[c] = Wfc2[c];
    }
    __syncthreads();
    int ig = i0 + il;
    float bi0 = boxes[ig*4+0], bi1 = boxes[ig*4+1], bi2 = boxes[ig*4+2], bi3 = boxes[ig*4+3];
    float4 G[4];
#pragma unroll
    for (int q = 0; q < 4; q++) {
        int jgl = j0 + jl + q;
        G[q] = make_float4(fabsf(bi0 - boxes[jgl*4+0]), fabsf(bi1 - boxes[jgl*4+1]),
                           fabsf(bi2 - boxes[jgl*4+2]), fabsf(bi3 - boxes[jgl*4+3]));
    }
    float acc[4] = {};
#pragma unroll 4
    for (int c = 0; c < HIDR; c++) {
        float  a  = sAb[il][c];
        float4 wg = sGeo[c];
        float  w2 = sW2[c];
        float4 b4 = *(const float4*)&sBt[c][jl];
        float v0 = a + b4.x + G[0].x*wg.x + G[0].y*wg.y + G[0].z*wg.z + G[0].w*wg.w;
        float v1 = a + b4.y + G[1].x*wg.x + G[1].y*wg.y + G[1].z*wg.z + G[1].w*wg.w;
        float v2 = a + b4.z + G[2].x*wg.x + G[2].y*wg.y + G[2].z*wg.z + G[2].w*wg.w;
        float v3 = a + b4.w + G[3].x*wg.x + G[3].y*wg.y + G[3].z*wg.z + G[3].w*wg.w;
        acc[0] += fmaxf(v0, 0.f) * w2;
        acc[1] += fmaxf(v1, 0.f) * w2;
        acc[2] += fmaxf(v2, 0.f) * w2;
        acc[3] += fmaxf(v3, 0.f) * w2;
    }
    float bb = bfc2[0];
#pragma unroll
    for (int q = 0; q < 4; q++)
        g_rel[(size_t)ig * NN + j0 + jl + q] = acc[q] + bb;
}

// ---------------- K3: warp-per-row top-4 (drop first) + W2 transpose -------
__global__ void k_topk(const float* __restrict__ W2) {
    int t = threadIdx.x;
    int lane = t & 31;
    int i = blockIdx.x * 8 + (t >> 5);   // row, grid 32 x 8 warps
    float v[8];
#pragma unroll
    for (int q = 0; q < 8; q++) v[q] = g_rel[i * NN + q * 32 + lane];
#pragma unroll
    for (int sel = 0; sel < TOPK + 1; sel++) {
        float bv = -INFINITY; int bi = 0;
#pragma unroll
        for (int q = 0; q < 8; q++) {
            int idx = q * 32 + lane;
            if (v[q] > bv) { bv = v[q]; bi = idx; }   // '>' keeps smallest idx in-lane
        }
#pragma unroll
        for (int o = 16; o; o >>= 1) {
            float ov = __shfl_down_sync(0xffffffffu, bv, o);
            int   oi = __shfl_down_sync(0xffffffffu, bi, o);
            if (ov > bv || (ov == bv && oi < bi)) { bv = ov; bi = oi; }  // tie -> smaller idx
        }
        bi = __shfl_sync(0xffffffffu, bi, 0);
        if (sel > 0 && lane == 0) g_top[i * TOPK + sel - 1] = bi;
        if ((bi & 31) == lane) v[bi >> 5] = -INFINITY;
    }
    // side job: transpose W2 into g_W2T (blocks 0..20, one row each)
    if (blockIdx.x < OUTD) {
        int o = blockIdx.x;
        for (int c = t; c < H1DIM; c += 256)
            g_W2T[o * H1DIM + c] = W2[c * OUTD + o];
    }
}

// ---------------- K4: CSR of incoming edges (parallel, deterministic) ------
__global__ void k_edges() {
    int t = threadIdx.x;                 // 1 block, 256 threads
    __shared__ int cnt[NN];
    __shared__ int off[NN];
    __shared__ int cur[NN];
    __shared__ int sInc[E_TOT];
    cnt[t] = 0;
    int tg[4];
    __syncthreads();
    tg[0] = g_top[t * TOPK + 0];
    tg[1] = g_top[t * TOPK + 1];
    tg[2] = g_top[t * TOPK + 2];
    tg[3] = t;                           // self loop
#pragma unroll
    for (int j = 0; j < 4; j++) atomicAdd(&cnt[tg[j]], 1);
    __syncthreads();
    off[t] = cnt[t];
    __syncthreads();
    for (int s = 1; s < NN; s <<= 1) {   // inclusive scan
        int v = (t >= s) ? off[t - s] : 0;
        __syncthreads();
        off[t] += v;
        __syncthreads();
    }
    g_off[t + 1] = off[t];
    if (t == 0) g_off[0] = 0;
    cur[t] = off[t] - cnt[t];            // exclusive offset
    __syncthreads();
#pragma unroll
    for (int j = 0; j < 4; j++) {
        int e = (j < 3) ? t * TOPK + j : NN * TOPK + t;
        int p = atomicAdd(&cur[tg[j]], 1);
        sInc[p] = e;
    }
    __syncthreads();
    // sort own bucket ascending -> deterministic, matches serial construction
    {
        int b = off[t] - cnt[t], n = cnt[t];
        for (int a = 1; a < n; a++) {
            int key = sInc[b + a];
            int k = a - 1;
            while (k >= 0 && sInc[b + k] > key) { sInc[b + k + 1] = sInc[b + k]; k--; }
            sInc[b + k + 1] = key;
        }
    }
    __syncthreads();
    for (int e = t; e < E_TOT; e += 256) g_inc[e] = sInc[e];
}

// ---------------- K5: h1 = [features | geomn] @ W1 (tiled GEMM) ------------
__global__ void k_gemm1(const float* __restrict__ feat,
                        const float* __restrict__ boxes,
                        const float* __restrict__ W1,
                        const void* img_h, const void* img_w) {
    __shared__ float  sA[16][33];
    __shared__ float4 sW[16][16];
    int t = threadIdx.x;
    int tx = t & 15, ty = t >> 4;
    int row0 = blockIdx.y * 32;
    int col0 = blockIdx.x * 64;
    float acc[2][4] = {};
    for (int k0 = 0; k0 < FEATD; k0 += 16) {
        if (t < 128) {
            int r = t >> 2, kq = t & 3;
            float4 v = *(const float4*)&feat[(size_t)(row0 + r) * FEATD + k0 + kq * 4];
            sA[kq*4+0][r] = v.x; sA[kq*4+1][r] = v.y; sA[kq*4+2][r] = v.z; sA[kq*4+3][r] = v.w;
        }
        {
            int kr = t >> 4, cq = t & 15;
            sW[kr][cq] = *(const float4*)&W1[(size_t)(k0 + kr) * H1DIM + col0 + cq * 4];
        }
        __syncthreads();
#pragma unroll
        for (int kk = 0; kk < 16; kk++) {
            float a0 = sA[kk][ty], a1 = sA[kk][ty + 16];
            float4 w = sW[kk][tx];
            acc[0][0] += a0 * w.x; acc[0][1] += a0 * w.y; acc[0][2] += a0 * w.z; acc[0][3] += a0 * w.w;
            acc[1][0] += a1 * w.x; acc[1][1] += a1 * w.y; acc[1][2] += a1 * w.z; acc[1][3] += a1 * w.w;
        }
        __syncthreads();
    }
    float fw = read_dim(img_w), fh = read_dim(img_h);
#pragma unroll
    for (int u = 0; u < 2; u++) {
        int n = row0 + ty + u * 16;
        float b0 = boxes[n*4+0] / fw, b1 = boxes[n*4+1] / fh;
        float b2 = boxes[n*4+2] / fw, b3 = boxes[n*4+3] / fh;
        float G[4] = { b0, b1, b2 - b0, b3 - b1 };
#pragma unroll
        for (int kk = 0; kk < 4; kk++) {
            const float* wr = &W1[(size_t)(FEATD + kk) * H1DIM + col0 + tx * 4];
            acc[u][0] += G[kk] * wr[0];
            acc[u][1] += G[kk] * wr[1];
            acc[u][2] += G[kk] * wr[2];
            acc[u][3] += G[kk] * wr[3];
        }
        *(float4*)&g_h1[(size_t)n * H1DIM + col0 + tx * 4] =
            make_float4(acc[u][0], acc[u][1], acc[u][2], acc[u][3]);
    }
}

// ---------------- K6: per-node per-head attention scores (layer 1) ---------
__global__ void k_score1(const float* __restrict__ a_src,
                         const float* __restrict__ a_dst) {
    int n = blockIdx.x;
    int hd = threadIdx.x >> 5, lane = threadIdx.x & 31;
    float s = 0.f, d = 0.f;
    for (int c = lane; c < GCH; c += 32) {
        float hv = g_h1[n * H1DIM + hd * GCH + c];
        s += hv * a_src[hd * GCH + c];
        d += hv * a_dst[hd * GCH + c];
    }
#pragma unroll
    for (int o = 16; o; o >>= 1) {
        s += __shfl_down_sync(0xffffffffu, s, o);
        d += __shfl_down_sync(0xffffffffu, d, o);
    }
    if (!lane) { g_ss1[n * HEADS + hd] = s; g_ds1[n * HEADS + hd] = d; }
}

// ---------------- K7: GAT1 softmax aggregation + bias + relu ---------------
__global__ void k_gat1(const float* __restrict__ b1) {
    int tnode = blockIdx.x, tid = threadIdx.x;
    int off = g_off[tnode], cnt = g_off[tnode + 1] - off;
    __shared__ float al[E_TOT * HEADS];
    for (int idx = tid; idx < cnt * HEADS; idx += blockDim.x) {
        int k = idx >> 2, hd = idx & 3;
        int sn = edge_src(g_inc[off + k]);
        float x = g_ss1[sn * HEADS + hd] + g_ds1[tnode * HEADS + hd];
        al[idx] = (x >= 0.f) ? x : 0.2f * x;   // leaky_relu 0.2
    }
    __syncthreads();
    if (tid < HEADS) {
        float m = -INFINITY;
        for (int k = 0; k < cnt; k++) m = fmaxf(m, al[k * HEADS + tid]);
        float s = 0.f;
        for (int k = 0; k < cnt; k++) { float p = expf(al[k * HEADS + tid] - m); al[k * HEADS + tid] = p; s += p; }
        float inv = 1.f / s;
        for (int k = 0; k < cnt; k++) al[k * HEADS + tid] *= inv;
    }
    __syncthreads();
    for (int o = tid; o < H1DIM; o += blockDim.x) {
        int hd = o >> 8;
        float acc = 0.f;
        for (int k = 0; k < cnt; k++) {
            int sn = edge_src(g_inc[off + k]);
            acc += al[k * HEADS + hd] * g_h1[sn * H1DIM + o];
        }
        g_x1[tnode * H1DIM + o] = fmaxf(acc + b1[o], 0.f);
    }
}

// ---------------- K8: h2 = x1 @ W2T + layer-2 attention scores -------------
__global__ void k_gemm2(const float* __restrict__ a_src,
                        const float* __restrict__ a_dst) {
    int n = blockIdx.x, t = threadIdx.x;     // 256 threads
    int w = t >> 5, lane = t & 31;
    __shared__ __align__(16) float sX[H1DIM];
    __shared__ float lg[OUTD];
    for (int c = t; c < H1DIM; c += 256) sX[c] = g_x1[n * H1DIM + c];
    __syncthreads();
    for (int o = w; o < OUTD; o += 8) {
        float acc = 0.f;
        const float* wr = &g_W2T[o * H1DIM];
        for (int c = lane; c < H1DIM; c += 32)
            acc += sX[c] * wr[c];
#pragma unroll
        for (int s = 16; s; s >>= 1) acc += __shfl_down_sync(0xffffffffu, acc, s);
        if (!lane) { g_h2[n * OUTD + o] = acc; lg[o] = acc; }
    }
    __syncthreads();
    if (t == 0) {
        float s = 0.f, d = 0.f;
        for (int oo = 0; oo < OUTD; oo++) {
            s += lg[oo] * a_src[oo];
            d += lg[oo] * a_dst[oo];
        }
        g_ss2[n] = s; g_ds2[n] = d;
    }
}

// ---------------- K10: GAT2 aggregate -> logits + argmax labels ------------
__global__ void k_gat2(const float* __restrict__ b2, float* __restrict__ out,
                       int out_size) {
    int tnode = blockIdx.x, tid = threadIdx.x;   // block of 32
    int off = g_off[tnode], cnt = g_off[tnode + 1] - off;
    __shared__ float al[E_TOT];
    __shared__ float lg[OUTD];
    for (int k = tid; k < cnt; k += 32) {
        int sn = edge_src(g_inc[off + k]);
        float x = g_ss2[sn] + g_ds2[tnode];
        al[k] = (x >= 0.f) ? x : 0.2f * x;
    }
    __syncthreads();
    if (tid == 0) {
        float m = -INFINITY;
        for (int k = 0; k < cnt; k++) m = fmaxf(m, al[k]);
        float s = 0.f;
        for (int k = 0; k < cnt; k++) { float p = expf(al[k] - m); al[k] = p; s += p; }
        float inv = 1.f / s;
        for (int k = 0; k < cnt; k++) al[k] *= inv;
    }
    __syncthreads();
    for (int o = tid; o < OUTD; o += 32) {
        float acc = 0.f;
        for (int k = 0; k < cnt; k++) {
            int sn = edge_src(g_inc[off + k]);
            acc += al[k] * g_h2[sn * OUTD + o];
        }
        float v = acc + b2[o];
        lg[o] = v;
        out[tnode * OUTD + o] = v;
    }
    __syncthreads();
    if (tid == 0 && out_size >= NN * OUTD + NN) {
        int best = 0;
        float bv = lg[0];
        for (int o = 1; o < OUTD; o++)
            if (lg[o] > bv) { bv = lg[o]; best = o; }
        out[NN * OUTD + tnode] = (float)best;
    }
}

// ---------------------------------------------------------------------------
extern "C" void kernel_launch(void* const* d_in, const int* in_sizes, int n_in,
                              void* d_out, int out_size) {
    const float* features = (const float*)d_in[0];
    const float* boxes    = (const float*)d_in[1];
    const float* W_fc1    = (const float*)d_in[2];
    const float* b_fc1    = (const float*)d_in[3];
    const float* W_fc2    = (const float*)d_in[4];
    const float* b_fc2    = (const float*)d_in[5];
    const float* W1       = (const float*)d_in[6];
    const float* a_src1   = (const float*)d_in[7];
    const float* a_dst1   = (const float*)d_in[8];
    const float* b1       = (const float*)d_in[9];
    const float* W2       = (const float*)d_in[10];
    const float* a_src2   = (const float*)d_in[11];
    const float* a_dst2   = (const float*)d_in[12];
    const float* b2       = (const float*)d_in[13];
    const void*  img_h    = d_in[14];
    const void*  img_w    = d_in[15];
    float* out = (float*)d_out;

    k_ab<<<dim3(8, 8), 256>>>(features, W_fc1);
    k_rel<<<dim3(4, 32), 128>>>(boxes, W_fc1, b_fc1, W_fc2, b_fc2);
    k_topk<<<32, 256>>>(W2);
    k_edges<<<1, NN>>>();
    k_gemm1<<<dim3(16, 8), 256>>>(features, boxes, W1, img_h, img_w);
    k_score1<<<NN, 128>>>(a_src1, a_dst1);
    k_gat1<<<NN, 256>>>(b1);
    k_gemm2<<<NN, 256>>>(a_src2, a_dst2);
    k_gat2<<<NN, 32>>>(b2, out, out_size);
}

// round 4
// speedup vs baseline: 1.4143x; 1.4143x over previous
#include <cuda_runtime.h>
#include <math.h>

#define NN    256
#define FEATD 1024
#define HIDR  256
#define HEADS 4
#define GCH   256
#define H1DIM 1024   // HEADS*GCH
#define OUTD  21
#define TOPK  3
#define E_TOT (NN*TOPK + NN)   // 1024 edges

// ---------------- scratch (device globals; no allocation allowed) ----------
__device__ __align__(16) float g_A[NN*HIDR];
__device__ __align__(16) float g_B[NN*HIDR];
__device__ __align__(16) float g_rel[NN*NN];
__device__ int   g_top[NN*TOPK];
__device__ int   g_off[NN+1];
__device__ int   g_inc[E_TOT];
__device__ __align__(16) float g_h1[NN*H1DIM];
__device__ float g_ss1[NN*HEADS], g_ds1[NN*HEADS];
__device__ __align__(16) float g_x1[NN*H1DIM];
__device__ __align__(16) float g_h2[NN*OUTD];
__device__ float g_ss2[NN], g_ds2[NN];
__device__ __align__(16) float g_W2T[OUTD*H1DIM];   // W2 transposed [o][c]

// edge id -> source node (edges 0..767 are topk from row e/3; 768.. are loops)
__device__ __forceinline__ int edge_src(int e) {
    return (e < NN * TOPK) ? (e / TOPK) : (e - NN * TOPK);
}

// read a scalar that may have been serialized as int32 or float32
__device__ __forceinline__ float read_dim(const void* p) {
    int iv = *(const int*)p;
    if (iv > 0 && iv < 100000) return (float)iv;
    return *(const float*)p;
}

// ---------------- K1: A = F @ W_fc1[0:1024], B = F @ W_fc1[1024:2048] ------
__global__ void k_ab(const float* __restrict__ feat, const float* __restrict__ Wfc1) {
    __shared__ float  sA[16][33];
    __shared__ float4 sW[16][16];
    int t = threadIdx.x;
    int tx = t & 15, ty = t >> 4;
    int row0 = blockIdx.y * 32;
    int colg = blockIdx.x * 64;
    const float* W;
    float* dst;
    int colL;
    if (colg < 256) { W = Wfc1;                       dst = g_A; colL = colg; }
    else            { W = Wfc1 + (size_t)1024 * HIDR; dst = g_B; colL = colg - 256; }
    float acc[2][4] = {};
    for (int k0 = 0; k0 < FEATD; k0 += 16) {
        if (t < 128) {
            int r = t >> 2, kq = t & 3;
            float4 v = *(const float4*)&feat[(size_t)(row0 + r) * FEATD + k0 + kq * 4];
            sA[kq*4+0][r] = v.x; sA[kq*4+1][r] = v.y; sA[kq*4+2][r] = v.z; sA[kq*4+3][r] = v.w;
        }
        {
            int kr = t >> 4, cq = t & 15;
            sW[kr][cq] = *(const float4*)&W[(size_t)(k0 + kr) * HIDR + colL + cq * 4];
        }
        __syncthreads();
#pragma unroll
        for (int kk = 0; kk < 16; kk++) {
            float a0 = sA[kk][ty], a1 = sA[kk][ty + 16];
            float4 w = sW[kk][tx];
            acc[0][0] += a0 * w.x; acc[0][1] += a0 * w.y; acc[0][2] += a0 * w.z; acc[0][3] += a0 * w.w;
            acc[1][0] += a1 * w.x; acc[1][1] += a1 * w.y; acc[1][2] += a1 * w.z; acc[1][3] += a1 * w.w;
        }
        __syncthreads();
    }
#pragma unroll
    for (int u = 0; u < 2; u++) {
        int r = row0 + ty + u * 16;
        *(float4*)&dst[(size_t)r * HIDR + colL + tx * 4] =
            make_float4(acc[u][0], acc[u][1], acc[u][2], acc[u][3]);
    }
}

// ---------------- K2: rel[i,j] = relu(A[i]+B[j]+bias+geom@Wg) . W_fc2 + b2 -
__global__ void k_rel(const float* __restrict__ boxes,
                      const float* __restrict__ Wfc1,
                      const float* __restrict__ bfc1,
                      const float* __restrict__ Wfc2,
                      const float* __restrict__ bfc2) {
    __shared__ __align__(16) float sAb[8][HIDR];
    __shared__ __align__(16) float sBt[HIDR][68];
    __shared__ __align__(16) float4 sGeo[HIDR];
    __shared__ float sW2[HIDR];
    int t = threadIdx.x;                 // 128
    int il = t >> 4, jg = t & 15, jl = jg * 4;
    int i0 = blockIdx.y * 8, j0 = blockIdx.x * 64;
    const float* Wg = Wfc1 + (size_t)2 * FEATD * HIDR;
    for (int idx = t; idx < 8 * HIDR; idx += 128) {
        int i = idx >> 8, c = idx & 255;
        sAb[i][c] = g_A[(size_t)(i0 + i) * HIDR + c] + bfc1[c];
    }
    for (int idx = t; idx < 64 * HIDR; idx += 128) {
        int j = idx >> 8, c = idx & 255;
        sBt[c][j] = g_B[(size_t)(j0 + j) * HIDR + c];
    }
    for (int c = t; c < HIDR; c += 128) {
        sGeo[c] = make_float4(Wg[c], Wg[HIDR + c], Wg[2 * HIDR + c], Wg[3 * HIDR + c]);
        sW2[c] = Wfc2[c];
    }
    __syncthreads();
    int ig = i0 + il;
    float bi0 = boxes[ig*4+0], bi1 = boxes[ig*4+1], bi2 = boxes[ig*4+2], bi3 = boxes[ig*4+3];
    float4 G[4];
#pragma unroll
    for (int q = 0; q < 4; q++) {
        int jgl = j0 + jl + q;
        G[q] = make_float4(fabsf(bi0 - boxes[jgl*4+0]), fabsf(bi1 - boxes[jgl*4+1]),
                           fabsf(bi2 - boxes[jgl*4+2]), fabsf(bi3 - boxes[jgl*4+3]));
    }
    float acc[4] = {};
#pragma unroll 4
    for (int c = 0; c < HIDR; c++) {
        float  a  = sAb[il][c];
        float4 wg = sGeo[c];
        float  w2 = sW2[c];
        float4 b4 = *(const float4*)&sBt[c][jl];
        float v0 = a + b4.x + G[0].x*wg.x + G[0].y*wg.y + G[0].z*wg.z + G[0].w*wg.w;
        float v1 = a + b4.y + G[1].x*wg.x + G[1].y*wg.y + G[1].z*wg.z + G[1].w*wg.w;
        float v2 = a + b4.z + G[2].x*wg.x + G[2].y*wg.y + G[2].z*wg.z + G[2].w*wg.w;
        float v3 = a + b4.w + G[3].x*wg.x + G[3].y*wg.y + G[3].z*wg.z + G[3].w*wg.w;
        acc[0] += fmaxf(v0, 0.f) * w2;
        acc[1] += fmaxf(v1, 0.f) * w2;
        acc[2] += fmaxf(v2, 0.f) * w2;
        acc[3] += fmaxf(v3, 0.f) * w2;
    }
    float bb = bfc2[0];
#pragma unroll
    for (int q = 0; q < 4; q++)
        g_rel[(size_t)ig * NN + j0 + jl + q] = acc[q] + bb;
}

// ---------------- K3: warp-per-row top-4 (drop first) + W2 transpose -------
__global__ void k_topk(const float* __restrict__ W2) {
    int t = threadIdx.x;
    int lane = t & 31;
    int i = blockIdx.x * 8 + (t >> 5);   // row, grid 32 x 8 warps
    float v[8];
#pragma unroll
    for (int q = 0; q < 8; q++) v[q] = g_rel[i * NN + q * 32 + lane];
#pragma unroll
    for (int sel = 0; sel < TOPK + 1; sel++) {
        float bv = -INFINITY; int bi = 0;
#pragma unroll
        for (int q = 0; q < 8; q++) {
            int idx = q * 32 + lane;
            if (v[q] > bv) { bv = v[q]; bi = idx; }   // '>' keeps smallest idx in-lane
        }
#pragma unroll
        for (int o = 16; o; o >>= 1) {
            float ov = __shfl_down_sync(0xffffffffu, bv, o);
            int   oi = __shfl_down_sync(0xffffffffu, bi, o);
            if (ov > bv || (ov == bv && oi < bi)) { bv = ov; bi = oi; }  // tie -> smaller idx
        }
        bi = __shfl_sync(0xffffffffu, bi, 0);
        if (sel > 0 && lane == 0) g_top[i * TOPK + sel - 1] = bi;
        if ((bi & 31) == lane) v[bi >> 5] = -INFINITY;
    }
    // side job: transpose W2 into g_W2T (blocks 0..20, one row each)
    if (blockIdx.x < OUTD) {
        int o = blockIdx.x;
        for (int c = t; c < H1DIM; c += 256)
            g_W2T[o * H1DIM + c] = W2[c * OUTD + o];
    }
}

// ---------------- K4: CSR build, sort-free, skew-immune, deterministic -----
// One block, 1024 threads = 1 thread per edge. Chunk = warp (32 ascending
// edge ids). Rank within bucket = (edges targeting same node in earlier
// chunks) + (same-target lanes below me in my chunk). Reproduces exact
// ascending-edge-id bucket order (== serial construction) with no sort.
__global__ void k_edges() {
    int t = threadIdx.x;                 // 0..1023
    int lane = t & 31, c = t >> 5;       // 32 chunks
    __shared__ int M[32][NN];            // chunk x node counts -> excl. prefixes
    __shared__ int off[NN];              // inclusive node offsets
    for (int idx = t; idx < 32 * NN; idx += 1024) ((int*)M)[idx] = 0;
    __syncthreads();
    int e = t;
    int tg = (e < NN * TOPK) ? g_top[e] : (e - NN * TOPK);
    unsigned same = __match_any_sync(0xffffffffu, tg);
    int rank = __popc(same & ((1u << lane) - 1u));
    if (rank == 0) M[c][tg] = __popc(same);   // leader lane writes chunk count
    __syncthreads();
    // per-node: exclusive prefix over chunks (in place) + node total
    if (t < NN) {
        int run = 0;
#pragma unroll
        for (int cc = 0; cc < 32; cc++) { int v = M[cc][t]; M[cc][t] = run; run += v; }
        off[t] = run;
    }
    __syncthreads();
    // inclusive scan over 256 node totals
    for (int s = 1; s < NN; s <<= 1) {
        int v = 0;
        if (t < NN && t >= s) v = off[t - s];
        __syncthreads();
        if (t < NN) off[t] += v;
        __syncthreads();
    }
    if (t < NN) {
        g_off[t + 1] = off[t];
        if (t == 0) g_off[0] = 0;
    }
    __syncthreads();
    int base = (tg == 0) ? 0 : off[tg - 1];
    g_inc[base + M[c][tg] + rank] = e;
}

// ---------------- K5: h1 = [features | geomn] @ W1 (tiled GEMM) ------------
__global__ void k_gemm1(const float* __restrict__ feat,
                        const float* __restrict__ boxes,
                        const float* __restrict__ W1,
                        const void* img_h, const void* img_w) {
    __shared__ float  sA[16][33];
    __shared__ float4 sW[16][16];
    int t = threadIdx.x;
    int tx = t & 15, ty = t >> 4;
    int row0 = blockIdx.y * 32;
    int col0 = blockIdx.x * 64;
    float acc[2][4] = {};
    for (int k0 = 0; k0 < FEATD; k0 += 16) {
        if (t < 128) {
            int r = t >> 2, kq = t & 3;
            float4 v = *(const float4*)&feat[(size_t)(row0 + r) * FEATD + k0 + kq * 4];
            sA[kq*4+0][r] = v.x; sA[kq*4+1][r] = v.y; sA[kq*4+2][r] = v.z; sA[kq*4+3][r] = v.w;
        }
        {
            int kr = t >> 4, cq = t & 15;
            sW[kr][cq] = *(const float4*)&W1[(size_t)(k0 + kr) * H1DIM + col0 + cq * 4];
        }
        __syncthreads();
#pragma unroll
        for (int kk = 0; kk < 16; kk++) {
            float a0 = sA[kk][ty], a1 = sA[kk][ty + 16];
            float4 w = sW[kk][tx];
            acc[0][0] += a0 * w.x; acc[0][1] += a0 * w.y; acc[0][2] += a0 * w.z; acc[0][3] += a0 * w.w;
            acc[1][0] += a1 * w.x; acc[1][1] += a1 * w.y; acc[1][2] += a1 * w.z; acc[1][3] += a1 * w.w;
        }
        __syncthreads();
    }
    float fw = read_dim(img_w), fh = read_dim(img_h);
#pragma unroll
    for (int u = 0; u < 2; u++) {
        int n = row0 + ty + u * 16;
        float b0 = boxes[n*4+0] / fw, b1 = boxes[n*4+1] / fh;
        float b2 = boxes[n*4+2] / fw, b3 = boxes[n*4+3] / fh;
        float G[4] = { b0, b1, b2 - b0, b3 - b1 };
#pragma unroll
        for (int kk = 0; kk < 4; kk++) {
            const float* wr = &W1[(size_t)(FEATD + kk) * H1DIM + col0 + tx * 4];
            acc[u][0] += G[kk] * wr[0];
            acc[u][1] += G[kk] * wr[1];
            acc[u][2] += G[kk] * wr[2];
            acc[u][3] += G[kk] * wr[3];
        }
        *(float4*)&g_h1[(size_t)n * H1DIM + col0 + tx * 4] =
            make_float4(acc[u][0], acc[u][1], acc[u][2], acc[u][3]);
    }
}

// ---------------- K6: per-node per-head attention scores (layer 1) ---------
__global__ void k_score1(const float* __restrict__ a_src,
                         const float* __restrict__ a_dst) {
    int n = blockIdx.x;
    int hd = threadIdx.x >> 5, lane = threadIdx.x & 31;
    float s = 0.f, d = 0.f;
    for (int c = lane; c < GCH; c += 32) {
        float hv = g_h1[n * H1DIM + hd * GCH + c];
        s += hv * a_src[hd * GCH + c];
        d += hv * a_dst[hd * GCH + c];
    }
#pragma unroll
    for (int o = 16; o; o >>= 1) {
        s += __shfl_down_sync(0xffffffffu, s, o);
        d += __shfl_down_sync(0xffffffffu, d, o);
    }
    if (!lane) { g_ss1[n * HEADS + hd] = s; g_ds1[n * HEADS + hd] = d; }
}

// ---------------- K7: GAT1 softmax aggregation + bias + relu ---------------
__global__ void k_gat1(const float* __restrict__ b1) {
    int tnode = blockIdx.x, tid = threadIdx.x;
    int off = g_off[tnode], cnt = g_off[tnode + 1] - off;
    __shared__ float al[E_TOT * HEADS];
    for (int idx = tid; idx < cnt * HEADS; idx += blockDim.x) {
        int k = idx >> 2, hd = idx & 3;
        int sn = edge_src(g_inc[off + k]);
        float x = g_ss1[sn * HEADS + hd] + g_ds1[tnode * HEADS + hd];
        al[idx] = (x >= 0.f) ? x : 0.2f * x;   // leaky_relu 0.2
    }
    __syncthreads();
    if (tid < HEADS) {
        float m = -INFINITY;
        for (int k = 0; k < cnt; k++) m = fmaxf(m, al[k * HEADS + tid]);
        float s = 0.f;
        for (int k = 0; k < cnt; k++) { float p = expf(al[k * HEADS + tid] - m); al[k * HEADS + tid] = p; s += p; }
        float inv = 1.f / s;
        for (int k = 0; k < cnt; k++) al[k * HEADS + tid] *= inv;
    }
    __syncthreads();
    for (int o = tid; o < H1DIM; o += blockDim.x) {
        int hd = o >> 8;
        float acc = 0.f;
        for (int k = 0; k < cnt; k++) {
            int sn = edge_src(g_inc[off + k]);
            acc += al[k * HEADS + hd] * g_h1[sn * H1DIM + o];
        }
        g_x1[tnode * H1DIM + o] = fmaxf(acc + b1[o], 0.f);
    }
}

// ---------------- K8: h2 = x1 @ W2T + layer-2 attention scores -------------
__global__ void k_gemm2(const float* __restrict__ a_src,
                        const float* __restrict__ a_dst) {
    int n = blockIdx.x, t = threadIdx.x;     // 256 threads
    int w = t >> 5, lane = t & 31;
    __shared__ __align__(16) float sX[H1DIM];
    __shared__ float lg[OUTD];
    for (int c = t; c < H1DIM; c += 256) sX[c] = g_x1[n * H1DIM + c];
    __syncthreads();
    for (int o = w; o < OUTD; o += 8) {
        float acc = 0.f;
        const float* wr = &g_W2T[o * H1DIM];
        for (int c = lane; c < H1DIM; c += 32)
            acc += sX[c] * wr[c];
#pragma unroll
        for (int s = 16; s; s >>= 1) acc += __shfl_down_sync(0xffffffffu, acc, s);
        if (!lane) { g_h2[n * OUTD + o] = acc; lg[o] = acc; }
    }
    __syncthreads();
    if (t == 0) {
        float s = 0.f, d = 0.f;
        for (int oo = 0; oo < OUTD; oo++) {
            s += lg[oo] * a_src[oo];
            d += lg[oo] * a_dst[oo];
        }
        g_ss2[n] = s; g_ds2[n] = d;
    }
}

// ---------------- K10: GAT2 aggregate -> logits + argmax labels ------------
__global__ void k_gat2(const float* __restrict__ b2, float* __restrict__ out,
                       int out_size) {
    int tnode = blockIdx.x, tid = threadIdx.x;   // block of 32
    int off = g_off[tnode], cnt = g_off[tnode + 1] - off;
    __shared__ float al[E_TOT];
    __shared__ float lg[OUTD];
    for (int k = tid; k < cnt; k += 32) {
        int sn = edge_src(g_inc[off + k]);
        float x = g_ss2[sn] + g_ds2[tnode];
        al[k] = (x >= 0.f) ? x : 0.2f * x;
    }
    __syncthreads();
    if (tid == 0) {
        float m = -INFINITY;
        for (int k = 0; k < cnt; k++) m = fmaxf(m, al[k]);
        float s = 0.f;
        for (int k = 0; k < cnt; k++) { float p = expf(al[k] - m); al[k] = p; s += p; }
        float inv = 1.f / s;
        for (int k = 0; k < cnt; k++) al[k] *= inv;
    }
    __syncthreads();
    for (int o = tid; o < OUTD; o += 32) {
        float acc = 0.f;
        for (int k = 0; k < cnt; k++) {
            int sn = edge_src(g_inc[off + k]);
            acc += al[k] * g_h2[sn * OUTD + o];
        }
        float v = acc + b2[o];
        lg[o] = v;
        out[tnode * OUTD + o] = v;
    }
    __syncthreads();
    if (tid == 0 && out_size >= NN * OUTD + NN) {
        int best = 0;
        float bv = lg[0];
        for (int o = 1; o < OUTD; o++)
            if (lg[o] > bv) { bv = lg[o]; best = o; }
        out[NN * OUTD + tnode] = (float)best;
    }
}

// ---------------------------------------------------------------------------
extern "C" void kernel_launch(void* const* d_in, const int* in_sizes, int n_in,
                              void* d_out, int out_size) {
    const float* features = (const float*)d_in[0];
    const float* boxes    = (const float*)d_in[1];
    const float* W_fc1    = (const float*)d_in[2];
    const float* b_fc1    = (const float*)d_in[3];
    const float* W_fc2    = (const float*)d_in[4];
    const float* b_fc2    = (const float*)d_in[5];
    const float* W1       = (const float*)d_in[6];
    const float* a_src1   = (const float*)d_in[7];
    const float* a_dst1   = (const float*)d_in[8];
    const float* b1       = (const float*)d_in[9];
    const float* W2       = (const float*)d_in[10];
    const float* a_src2   = (const float*)d_in[11];
    const float* a_dst2   = (const float*)d_in[12];
    const float* b2       = (const float*)d_in[13];
    const void*  img_h    = d_in[14];
    const void*  img_w    = d_in[15];
    float* out = (float*)d_out;

    k_ab<<<dim3(8, 8), 256>>>(features, W_fc1);
    k_rel<<<dim3(4, 32), 128>>>(boxes, W_fc1, b_fc1, W_fc2, b_fc2);
    k_topk<<<32, 256>>>(W2);
    k_edges<<<1, 1024>>>();
    k_gemm1<<<dim3(16, 8), 256>>>(features, boxes, W1, img_h, img_w);
    k_score1<<<NN, 128>>>(a_src1, a_dst1);
    k_gat1<<<NN, 256>>>(b1);
    k_gemm2<<<NN, 256>>>(a_src2, a_dst2);
    k_gat2<<<NN, 32>>>(b2, out, out_size);
}